// round 1
// baseline (speedup 1.0000x reference)
#include <cuda_runtime.h>
#include <cstdint>

#define T_STEPS 16
#define AA 64
#define BB 64
#define NN 12
#define BATCH 4096
#define ZS 100
#define ENC 400
#define DEC 400

// ---------------- device scratch (no allocs allowed) ----------------
__device__ float g_henc[BATCH * ENC];
__device__ float g_senc[BATCH * ENC];
__device__ float g_hdec[BATCH * DEC];
__device__ float g_sdec[BATCH * DEC];
__device__ float g_encin[BATCH * 1088];   // [r(288) | h_dec(400) | h_enc(400)]
__device__ float g_decin[BATCH * 500];    // [z(100) | h_dec(400)]
__device__ float g_gates[BATCH * 1600];
__device__ float g_musig[BATCH * 200];    // [mu(100) | logsig(100)]
__device__ float g_Fx[BATCH * NN * AA];
__device__ float g_Fy[BATCH * NN * BB];
__device__ float g_gamma[BATCH];
__device__ float g_wr[BATCH * NN * NN];

__device__ __forceinline__ float sigm(float x) { return 1.0f / (1.0f + expf(-x)); }

// ---------------- zero ----------------
__global__ void zero_kernel(float* p, int n) {
    int i = blockIdx.x * blockDim.x + threadIdx.x;
    int stride = gridDim.x * blockDim.x;
    for (; i < n; i += stride) p[i] = 0.0f;
}

// ---------------- attention filters ----------------
// one block per batch row, 128 threads
__global__ void attn_kernel(const float* __restrict__ hdec,
                            const float* __restrict__ w_attn,
                            const float* __restrict__ b_attn,
                            float* __restrict__ Fx, float* __restrict__ Fy,
                            float* __restrict__ gma,
                            const float* __restrict__ henc,
                            float* __restrict__ encin, int copy_states)
{
    int b = blockIdx.x;
    int tid = threadIdx.x;
    __shared__ float red[5][129];
    __shared__ float p[5];
    __shared__ float Fbuf[NN * 64];
    __shared__ float rsum[NN];

    const float* h = hdec + (size_t)b * DEC;
    float acc[5] = {0.f, 0.f, 0.f, 0.f, 0.f};
    for (int k = tid; k < DEC; k += 128) {
        float hv = h[k];
#pragma unroll
        for (int j = 0; j < 5; j++) acc[j] += hv * w_attn[j * DEC + k];
    }
#pragma unroll
    for (int j = 0; j < 5; j++) red[j][tid] = acc[j];
    __syncthreads();
    if (tid < 5) {
        float s = 0.f;
        for (int i = 0; i < 128; i++) s += red[tid][i];
        p[tid] = s + b_attn[tid];
    }
    __syncthreads();

    float gx     = 32.5f * (p[0] + 1.0f);       // (A+1)/2 * (gx_+1)
    float gy     = 32.5f * (p[1] + 1.0f);
    float sigma2 = expf(p[2]);
    float delta  = (63.0f / 11.0f) * expf(p[3]);
    float gamma  = expf(p[4]);
    float inv2s2 = 1.0f / (2.0f * sigma2);

    // Fx: rows n=0..11, cols a=0..63
    for (int e = tid; e < NN * 64; e += 128) {
        int n = e >> 6, a = e & 63;
        float mu = ((float)n - 6.5f) * delta + gx;
        float t = ((float)a - mu) * inv2s2;
        Fbuf[e] = expf(-t * t);
    }
    __syncthreads();
    if (tid < NN) {
        float s = 0.f;
        for (int a = 0; a < 64; a++) s += Fbuf[tid * 64 + a];
        rsum[tid] = 1.0f / (s + 1e-9f);
    }
    __syncthreads();
    for (int e = tid; e < NN * 64; e += 128)
        Fx[(size_t)b * (NN * 64) + e] = Fbuf[e] * rsum[e >> 6];
    __syncthreads();

    // Fy
    for (int e = tid; e < NN * 64; e += 128) {
        int n = e >> 6, a = e & 63;
        float mu = ((float)n - 6.5f) * delta + gy;
        float t = ((float)a - mu) * inv2s2;
        Fbuf[e] = expf(-t * t);
    }
    __syncthreads();
    if (tid < NN) {
        float s = 0.f;
        for (int a = 0; a < 64; a++) s += Fbuf[tid * 64 + a];
        rsum[tid] = 1.0f / (s + 1e-9f);
    }
    __syncthreads();
    for (int e = tid; e < NN * 64; e += 128)
        Fy[(size_t)b * (NN * 64) + e] = Fbuf[e] * rsum[e >> 6];

    if (tid == 0) gma[b] = gamma;

    if (copy_states) {
        float* ei = encin + (size_t)b * 1088;
        const float* he = henc + (size_t)b * ENC;
        for (int k = tid; k < 400; k += 128) {
            ei[288 + k] = h[k];
            ei[688 + k] = he[k];
        }
    }
}

// ---------------- glimpse (read) ----------------
// one block per batch row, 256 threads
__global__ void glimpse_kernel(const float* __restrict__ x,
                               const float* __restrict__ c,
                               const float* __restrict__ Fxg,
                               const float* __restrict__ Fyg,
                               const float* __restrict__ gma,
                               float* __restrict__ encin)
{
    int b = blockIdx.x;
    int tid = threadIdx.x;
    __shared__ float xs[4096];
    __shared__ float xh[4096];
    __shared__ float sFy[NN * 64];
    __shared__ float sFx[NN * 65];       // padded stride 65
    __shared__ float tmp[2][NN * 64];

    const float* xb = x + (size_t)b * 4096;
    const float* cb = c + (size_t)b * 4096;
    for (int i = tid; i < 4096; i += 256) {
        float xv = xb[i];
        float cv = cb[i];
        xs[i] = xv;
        xh[i] = xv - sigm(cv);
    }
    for (int i = tid; i < NN * 64; i += 256) {
        sFy[i] = Fyg[(size_t)b * (NN * 64) + i];
        int n = i >> 6, a = i & 63;
        sFx[n * 65 + a] = Fxg[(size_t)b * (NN * 64) + i];
    }
    __syncthreads();

    // tmp[img][n][a] = sum_B Fy[n][B] * img[B][a]
    for (int e = tid; e < 2 * NN * 64; e += 256) {
        int img = (e >= NN * 64) ? 1 : 0;
        int rem = e - img * NN * 64;
        int n = rem >> 6, a = rem & 63;
        const float* src = img ? xh : xs;
        const float* fyr = &sFy[n * 64];
        float acc = 0.f;
#pragma unroll 8
        for (int bi = 0; bi < 64; bi++) acc += fyr[bi] * src[bi * 64 + a];
        tmp[img][rem] = acc;
    }
    __syncthreads();

    float gamma = gma[b];
    // r[img][n][m] = sum_a tmp[img][n][a] * Fx[m][a]
    for (int o = tid; o < 2 * NN * NN; o += 256) {
        int img = (o >= NN * NN) ? 1 : 0;
        int rem = o - img * NN * NN;
        int n = rem / NN, m = rem % NN;
        const float* tr = &tmp[img][n * 64];
        const float* fxr = &sFx[m * 65];
        float acc = 0.f;
#pragma unroll 8
        for (int a = 0; a < 64; a++) acc += tr[a] * fxr[a];
        encin[(size_t)b * 1088 + o] = acc * gamma;
    }
}

// ---------------- canvas write ----------------
// one block per batch row, 256 threads
__global__ void write_kernel(const float* __restrict__ wrg,
                             const float* __restrict__ Fxg,
                             const float* __restrict__ Fyg,
                             const float* __restrict__ gma,
                             float* __restrict__ c)
{
    int b = blockIdx.x;
    int tid = threadIdx.x;
    __shared__ float sFy[NN * 64];
    __shared__ float sFx[NN * 64];
    __shared__ float sw[NN * NN];
    __shared__ float tmp[NN * 64];       // tmp[m][Bi]

    for (int i = tid; i < NN * 64; i += 256) {
        sFy[i] = Fyg[(size_t)b * (NN * 64) + i];
        sFx[i] = Fxg[(size_t)b * (NN * 64) + i];
    }
    if (tid < NN * NN) sw[tid] = wrg[(size_t)b * (NN * NN) + tid];
    __syncthreads();

    // tmp[m][Bi] = sum_n Fy[n][Bi] * w[n][m]
    for (int e = tid; e < NN * 64; e += 256) {
        int m = e >> 6, Bi = e & 63;
        float acc = 0.f;
#pragma unroll
        for (int n = 0; n < NN; n++) acc += sFy[n * 64 + Bi] * sw[n * NN + m];
        tmp[e] = acc;
    }
    __syncthreads();

    float invg = 1.0f / gma[b];
    float* cb = c + (size_t)b * 4096;
    for (int p = tid; p < 4096; p += 256) {
        int Bi = p >> 6, Ai = p & 63;
        float acc = 0.f;
#pragma unroll
        for (int m = 0; m < NN; m++) acc += tmp[m * 64 + Bi] * sFx[m * 64 + Ai];
        cb[p] += acc * invg;
    }
}

// ---------------- GEMM: C = A @ [W1|W2]^T + b1 + b2 ----------------
// A: M x Ktot row-major (lda), W1: Nout x K1 row-major, W2: Nout x K2.
// K1, Ktot multiples of 4. M multiple of 128.
#define BM 128
#define BN 64
#define BK 16

__global__ __launch_bounds__(256) void gemm2seg(
    const float* __restrict__ A, int lda, int Ktot,
    const float* __restrict__ W1, int K1,
    const float* __restrict__ W2, int K2,
    const float* __restrict__ b1, const float* __restrict__ b2,
    float* __restrict__ C, int ldc, int Nout)
{
    __shared__ float As[BK][BM + 1];
    __shared__ float Ws[BK][BN + 1];

    int m0 = blockIdx.y * BM;
    int n0 = blockIdx.x * BN;
    int tid = threadIdx.x;
    int tm = tid >> 4;       // 0..15
    int tn = tid & 15;       // 0..15

    float acc[8][4];
#pragma unroll
    for (int r = 0; r < 8; r++)
#pragma unroll
        for (int cc = 0; cc < 4; cc++) acc[r][cc] = 0.f;

    int K12 = K1 + K2;

    for (int k0 = 0; k0 < Ktot; k0 += BK) {
        // A tile: 128 x 16 = 512 float4
#pragma unroll
        for (int i = 0; i < 2; i++) {
            int idx = tid + i * 256;
            int row = idx >> 2;
            int kq = (idx & 3) * 4;
            int kg = k0 + kq;
            float4 v = make_float4(0.f, 0.f, 0.f, 0.f);
            if (kg < Ktot)
                v = *(const float4*)(A + (size_t)(m0 + row) * lda + kg);
            As[kq + 0][row] = v.x;
            As[kq + 1][row] = v.y;
            As[kq + 2][row] = v.z;
            As[kq + 3][row] = v.w;
        }
        // W tile: 64 x 16 = 256 float4
        {
            int j = tid >> 2;
            int kq = (tid & 3) * 4;
            int kg = k0 + kq;
            int jn = n0 + j;
            float4 v = make_float4(0.f, 0.f, 0.f, 0.f);
            if (jn < Nout) {
                if (kg < K1)
                    v = *(const float4*)(W1 + (size_t)jn * K1 + kg);
                else if (kg < K12)
                    v = *(const float4*)(W2 + (size_t)jn * K2 + (kg - K1));
            }
            Ws[kq + 0][j] = v.x;
            Ws[kq + 1][j] = v.y;
            Ws[kq + 2][j] = v.z;
            Ws[kq + 3][j] = v.w;
        }
        __syncthreads();

#pragma unroll
        for (int k = 0; k < BK; k++) {
            float av[8], bv[4];
#pragma unroll
            for (int r = 0; r < 8; r++) av[r] = As[k][tm + 16 * r];
#pragma unroll
            for (int cc = 0; cc < 4; cc++) bv[cc] = Ws[k][tn + 16 * cc];
#pragma unroll
            for (int r = 0; r < 8; r++)
#pragma unroll
                for (int cc = 0; cc < 4; cc++) acc[r][cc] += av[r] * bv[cc];
        }
        __syncthreads();
    }

#pragma unroll
    for (int r = 0; r < 8; r++) {
        int m = m0 + tm + 16 * r;
#pragma unroll
        for (int cc = 0; cc < 4; cc++) {
            int n = n0 + tn + 16 * cc;
            if (n < Nout) {
                float v = acc[r][cc];
                if (b1) v += b1[n];
                if (b2) v += b2[n];
                C[(size_t)m * ldc + n] = v;
            }
        }
    }
}

// ---------------- LSTM pointwise ----------------
__global__ void lstm_pw(const float* __restrict__ gates,
                        float* __restrict__ h, float* __restrict__ s)
{
    int idx = blockIdx.x * blockDim.x + threadIdx.x;
    int total = BATCH * 400;
    if (idx >= total) return;
    int b = idx / 400, u = idx - b * 400;
    const float* g = gates + (size_t)b * 1600;
    float gi = g[u], gf = g[400 + u], gg = g[800 + u], go = g[1200 + u];
    float sv = s[idx];
    float c2 = sigm(gf) * sv + sigm(gi) * tanhf(gg);
    float h2 = sigm(go) * tanhf(c2);
    s[idx] = c2;
    h[idx] = h2;
}

// ---------------- z + decoder input assembly ----------------
__global__ void z_kernel(const float* __restrict__ musig,
                         const float* __restrict__ eps_t,
                         const float* __restrict__ hdec,
                         float* __restrict__ decin)
{
    int idx = blockIdx.x * blockDim.x + threadIdx.x;
    int total = BATCH * 500;
    if (idx >= total) return;
    int b = idx / 500, j = idx - b * 500;
    float v;
    if (j < 100) {
        float mu = musig[(size_t)b * 200 + j];
        float ls = musig[(size_t)b * 200 + 100 + j];
        v = mu + expf(ls) * eps_t[(size_t)b * 100 + j];
    } else {
        v = hdec[(size_t)b * 400 + (j - 100)];
    }
    decin[idx] = v;
}

// ---------------- host launcher ----------------
extern "C" void kernel_launch(void* const* d_in, const int* in_sizes, int n_in,
                              void* d_out, int out_size)
{
    const float* x        = (const float*)d_in[0];
    const float* eps      = (const float*)d_in[1];
    const float* w_enc_ih = (const float*)d_in[2];
    const float* w_enc_hh = (const float*)d_in[3];
    const float* b_enc_ih = (const float*)d_in[4];
    const float* b_enc_hh = (const float*)d_in[5];
    const float* w_dec_ih = (const float*)d_in[6];
    const float* w_dec_hh = (const float*)d_in[7];
    const float* b_dec_ih = (const float*)d_in[8];
    const float* b_dec_hh = (const float*)d_in[9];
    const float* w_mu     = (const float*)d_in[10];
    const float* b_mu     = (const float*)d_in[11];
    const float* w_sig    = (const float*)d_in[12];
    const float* b_sig    = (const float*)d_in[13];
    const float* w_attn   = (const float*)d_in[14];
    const float* b_attn   = (const float*)d_in[15];
    const float* w_write  = (const float*)d_in[16];
    const float* b_write  = (const float*)d_in[17];
    float* c = (float*)d_out;

    float *p_henc, *p_senc, *p_hdec, *p_sdec, *p_encin, *p_decin;
    float *p_gates, *p_musig, *p_Fx, *p_Fy, *p_gamma, *p_wr;
    cudaGetSymbolAddress((void**)&p_henc,  g_henc);
    cudaGetSymbolAddress((void**)&p_senc,  g_senc);
    cudaGetSymbolAddress((void**)&p_hdec,  g_hdec);
    cudaGetSymbolAddress((void**)&p_sdec,  g_sdec);
    cudaGetSymbolAddress((void**)&p_encin, g_encin);
    cudaGetSymbolAddress((void**)&p_decin, g_decin);
    cudaGetSymbolAddress((void**)&p_gates, g_gates);
    cudaGetSymbolAddress((void**)&p_musig, g_musig);
    cudaGetSymbolAddress((void**)&p_Fx,    g_Fx);
    cudaGetSymbolAddress((void**)&p_Fy,    g_Fy);
    cudaGetSymbolAddress((void**)&p_gamma, g_gamma);
    cudaGetSymbolAddress((void**)&p_wr,    g_wr);

    // init: zero canvas + states
    zero_kernel<<<4096, 256>>>(c, BATCH * AA * BB);
    zero_kernel<<<1024, 256>>>(p_henc, BATCH * ENC);
    zero_kernel<<<1024, 256>>>(p_senc, BATCH * ENC);
    zero_kernel<<<1024, 256>>>(p_hdec, BATCH * DEC);
    zero_kernel<<<1024, 256>>>(p_sdec, BATCH * DEC);

    dim3 gemm_blk(256);
    dim3 grid_enc(25, 32);   // Nout=1600, M=4096
    dim3 grid_dec(25, 32);
    dim3 grid_ms(2, 32);     // Nout=100
    dim3 grid_wr(3, 32);     // Nout=144

    for (int t = 0; t < T_STEPS; t++) {
        // attention #1 (+ copy h_dec, h_enc into enc input)
        attn_kernel<<<BATCH, 128>>>(p_hdec, w_attn, b_attn, p_Fx, p_Fy, p_gamma,
                                    p_henc, p_encin, 1);
        // glimpse -> enc_in[:, 0:288]
        glimpse_kernel<<<BATCH, 256>>>(x, c, p_Fx, p_Fy, p_gamma, p_encin);
        // encoder gates
        gemm2seg<<<grid_enc, gemm_blk>>>(p_encin, 1088, 1088,
                                         w_enc_ih, 688, w_enc_hh, 400,
                                         b_enc_ih, b_enc_hh,
                                         p_gates, 1600, 1600);
        lstm_pw<<<(BATCH * 400 + 255) / 256, 256>>>(p_gates, p_henc, p_senc);
        // mu / logsig
        gemm2seg<<<grid_ms, gemm_blk>>>(p_henc, 400, 400,
                                        w_mu, 400, (const float*)nullptr, 0,
                                        b_mu, (const float*)nullptr,
                                        p_musig, 200, 100);
        gemm2seg<<<grid_ms, gemm_blk>>>(p_henc, 400, 400,
                                        w_sig, 400, (const float*)nullptr, 0,
                                        b_sig, (const float*)nullptr,
                                        p_musig + 100, 200, 100);
        // z and decoder input
        z_kernel<<<(BATCH * 500 + 255) / 256, 256>>>(
            p_musig, eps + (size_t)t * BATCH * ZS, p_hdec, p_decin);
        // decoder gates
        gemm2seg<<<grid_dec, gemm_blk>>>(p_decin, 500, 500,
                                         w_dec_ih, 100, w_dec_hh, 400,
                                         b_dec_ih, b_dec_hh,
                                         p_gates, 1600, 1600);
        lstm_pw<<<(BATCH * 400 + 255) / 256, 256>>>(p_gates, p_hdec, p_sdec);
        // attention #2
        attn_kernel<<<BATCH, 128>>>(p_hdec, w_attn, b_attn, p_Fx, p_Fy, p_gamma,
                                    p_henc, p_encin, 0);
        // write patch
        gemm2seg<<<grid_wr, gemm_blk>>>(p_hdec, 400, 400,
                                        w_write, 400, (const float*)nullptr, 0,
                                        b_write, (const float*)nullptr,
                                        p_wr, 144, 144);
        // canvas update
        write_kernel<<<BATCH, 256>>>(p_wr, p_Fx, p_Fy, p_gamma, c);
    }
}

// round 4
// speedup vs baseline: 1.2002x; 1.2002x over previous
#include <cuda_runtime.h>
#include <cstdint>

#define T_STEPS 16
#define AA 64
#define BB 64
#define NN 12
#define BATCH 4096
#define ZS 100
#define ENC 400
#define DEC 400

// ---------------- device scratch (no allocs allowed) ----------------
__device__ float g_henc[BATCH * ENC];
__device__ float g_senc[BATCH * ENC];
__device__ float g_hdec[BATCH * DEC];
__device__ float g_sdec[BATCH * DEC];
__device__ float g_encin[BATCH * 1088];   // [r(288) | h_dec(400) | h_enc(400)]
__device__ float g_decin[BATCH * 512];    // [z(100) | h_dec(400) | pad(12)]
__device__ float g_gates[BATCH * 1600];
__device__ float g_musig[BATCH * 200];    // [mu(100) | logsig(100)]
__device__ float g_Fx[BATCH * NN * AA];
__device__ float g_Fy[BATCH * NN * BB];
__device__ float g_gamma[BATCH];
__device__ float g_wr[BATCH * NN * NN];

__device__ __forceinline__ float sigm(float x) { return 1.0f / (1.0f + expf(-x)); }

__device__ __forceinline__ uint32_t f2tf32(float x) {
    uint32_t r;
    asm("cvt.rna.tf32.f32 %0, %1;" : "=r"(r) : "f"(x));
    return r;
}

__device__ __forceinline__ void mma_tf32(float* d, const uint32_t* a, const uint32_t* b) {
    asm volatile(
        "mma.sync.aligned.m16n8k8.row.col.f32.tf32.tf32.f32 "
        "{%0,%1,%2,%3}, {%4,%5,%6,%7}, {%8,%9}, {%0,%1,%2,%3};\n"
        : "+f"(d[0]), "+f"(d[1]), "+f"(d[2]), "+f"(d[3])
        : "r"(a[0]), "r"(a[1]), "r"(a[2]), "r"(a[3]), "r"(b[0]), "r"(b[1]));
}

// ================= tensor-core GEMM (3xTF32 mma.sync, ~fp32 accuracy) =======
// C[M, Nout] = A[M, Ktot] @ [W1 | W2]^T + b1 (+ b2)
// A row-major (lda), W row-major (Nout x K). M mult of 128.
// Block tile 128x64x32, 256 threads (8 warps: 4 along M, 2 along N).
// Each operand split hi/lo (tf32 + residual); 3 MMAs per product for fp32-like
// precision. SMEM: As[k][m] stride 136, Bs[k][n] stride 72, XOR (x ^ (k & 28)).
#define A_PLANE 4352                       // 32*136 words
#define B_PLANE 2304                       // 32*72 words
#define GEMM_SMEM_BYTES ((4 * A_PLANE + 4 * B_PLANE + 64) * 4)

__global__ __launch_bounds__(256) void gemm_mma(
    const float* __restrict__ A, int lda, int Ktot,
    const float* __restrict__ W1, int K1,
    const float* __restrict__ W2, int K2,
    const float* __restrict__ b1, const float* __restrict__ b2,
    float* __restrict__ C, int ldc, int Nout)
{
    extern __shared__ uint32_t sm[];
    uint32_t* Asb = sm;                          // 2 bufs x (hi,lo) planes
    uint32_t* Bsb = sm + 4 * A_PLANE;
    float* sbias = (float*)(sm + 4 * A_PLANE + 4 * B_PLANE);

    const int tid  = threadIdx.x;
    const int lane = tid & 31;
    const int w    = tid >> 5;
    const int r    = lane >> 2;          // 0..7
    const int j    = lane & 3;           // 0..3
    const int wm   = (w >> 1) * 32;      // warp M offset in tile
    const int wn   = (w & 1) * 32;       // warp N offset in tile
    const int m0   = blockIdx.y * 128;
    const int n0   = blockIdx.x * 64;
    const int K12  = K1 + K2;
    const int S    = (Ktot + 31) >> 5;

    if (tid < 64) {
        int n = n0 + tid;
        float bv = 0.f;
        if (n < Nout) { bv = b1[n]; if (b2) bv += b2[n]; }
        sbias[tid] = bv;
    }

    float d[2][4][4];
#pragma unroll
    for (int mi = 0; mi < 2; mi++)
#pragma unroll
        for (int ni = 0; ni < 4; ni++)
#pragma unroll
            for (int q = 0; q < 4; q++) d[mi][ni][q] = 0.f;

    float4 pa[4];
    float4 pb[2];
    const float4 f4z = make_float4(0.f, 0.f, 0.f, 0.f);

#define LOAD_GLOBAL(s) {                                                         \
    int k0g = (s) << 5;                                                          \
    _Pragma("unroll")                                                            \
    for (int cI = 0; cI < 4; cI++) {                                             \
        int fidx = tid + (cI << 8);                                              \
        int m = fidx >> 3;                                                       \
        int kg = k0g + ((fidx & 7) << 2);                                        \
        pa[cI] = (kg < Ktot)                                                     \
            ? *(const float4*)(A + (size_t)(m0 + m) * lda + kg) : f4z;           \
    }                                                                            \
    _Pragma("unroll")                                                            \
    for (int cI = 0; cI < 2; cI++) {                                             \
        int fidx = tid + (cI << 8);                                              \
        int n = fidx >> 3;                                                       \
        int kg = k0g + ((fidx & 7) << 2);                                        \
        float4 v = f4z;                                                          \
        int ng = n0 + n;                                                         \
        if (ng < Nout) {                                                         \
            if (kg < K1)       v = *(const float4*)(W1 + (size_t)ng * K1 + kg);  \
            else if (kg < K12) v = *(const float4*)(W2 + (size_t)ng * K2 + (kg - K1)); \
        }                                                                        \
        pb[cI] = v;                                                              \
    } }

#define STORE_SMEM(buf) {                                                        \
    uint32_t* abh = Asb + (buf) * (2 * A_PLANE);                                 \
    uint32_t* abl = abh + A_PLANE;                                               \
    uint32_t* bbh = Bsb + (buf) * (2 * B_PLANE);                                 \
    uint32_t* bbl = bbh + B_PLANE;                                               \
    _Pragma("unroll")                                                            \
    for (int cI = 0; cI < 4; cI++) {                                             \
        int fidx = tid + (cI << 8);                                              \
        int m = fidx >> 3;                                                       \
        int kq = (fidx & 7) << 2;                                                \
        const float* pv = (const float*)&pa[cI];                                 \
        _Pragma("unroll")                                                        \
        for (int u = 0; u < 4; u++) {                                            \
            int k = kq + u;                                                      \
            int idx = k * 136 + (m ^ (k & 28));                                  \
            uint32_t hi = f2tf32(pv[u]);                                         \
            abh[idx] = hi;                                                       \
            abl[idx] = f2tf32(pv[u] - __uint_as_float(hi));                      \
        }                                                                        \
    }                                                                            \
    _Pragma("unroll")                                                            \
    for (int cI = 0; cI < 2; cI++) {                                             \
        int fidx = tid + (cI << 8);                                              \
        int n = fidx >> 3;                                                       \
        int kq = (fidx & 7) << 2;                                                \
        const float* pv = (const float*)&pb[cI];                                 \
        _Pragma("unroll")                                                        \
        for (int u = 0; u < 4; u++) {                                            \
            int k = kq + u;                                                      \
            int idx = k * 72 + (n ^ (k & 28));                                   \
            uint32_t hi = f2tf32(pv[u]);                                         \
            bbh[idx] = hi;                                                       \
            bbl[idx] = f2tf32(pv[u] - __uint_as_float(hi));                      \
        }                                                                        \
    } }

#define COMPUTE(buf) {                                                           \
    const uint32_t* abh = Asb + (buf) * (2 * A_PLANE);                           \
    const uint32_t* abl = abh + A_PLANE;                                         \
    const uint32_t* bbh = Bsb + (buf) * (2 * B_PLANE);                           \
    const uint32_t* bbl = bbh + B_PLANE;                                         \
    _Pragma("unroll")                                                            \
    for (int kk = 0; kk < 32; kk += 8) {                                         \
        int k0j = kk + j, k1j = k0j + 4;                                         \
        int f0 = k0j & 28, f1 = k1j & 28;                                        \
        uint32_t afh[2][4], afl[2][4];                                           \
        uint32_t bfh[4][2], bfl[4][2];                                           \
        _Pragma("unroll")                                                        \
        for (int mi = 0; mi < 2; mi++) {                                         \
            int mb = wm + mi * 16 + r;                                           \
            int i00 = k0j * 136 + (mb ^ f0);                                     \
            int i01 = k0j * 136 + ((mb + 8) ^ f0);                               \
            int i10 = k1j * 136 + (mb ^ f1);                                     \
            int i11 = k1j * 136 + ((mb + 8) ^ f1);                               \
            afh[mi][0] = abh[i00]; afh[mi][1] = abh[i01];                        \
            afh[mi][2] = abh[i10]; afh[mi][3] = abh[i11];                        \
            afl[mi][0] = abl[i00]; afl[mi][1] = abl[i01];                        \
            afl[mi][2] = abl[i10]; afl[mi][3] = abl[i11];                        \
        }                                                                        \
        _Pragma("unroll")                                                        \
        for (int ni = 0; ni < 4; ni++) {                                         \
            int nb = wn + ni * 8 + r;                                            \
            int i0 = k0j * 72 + (nb ^ f0);                                       \
            int i1 = k1j * 72 + (nb ^ f1);                                       \
            bfh[ni][0] = bbh[i0]; bfh[ni][1] = bbh[i1];                          \
            bfl[ni][0] = bbl[i0]; bfl[ni][1] = bbl[i1];                          \
        }                                                                        \
        _Pragma("unroll")                                                        \
        for (int mi = 0; mi < 2; mi++)                                           \
            _Pragma("unroll")                                                    \
            for (int ni = 0; ni < 4; ni++) {                                     \
                mma_tf32(d[mi][ni], afh[mi], bfl[ni]);                           \
                mma_tf32(d[mi][ni], afl[mi], bfh[ni]);                           \
                mma_tf32(d[mi][ni], afh[mi], bfh[ni]);                           \
            }                                                                    \
    } }

    LOAD_GLOBAL(0);
    STORE_SMEM(0);
    __syncthreads();

    for (int s = 1; s < S; s++) {
        LOAD_GLOBAL(s);
        COMPUTE((s - 1) & 1);
        STORE_SMEM(s & 1);
        __syncthreads();
    }
    COMPUTE((S - 1) & 1);

    // epilogue
#pragma unroll
    for (int mi = 0; mi < 2; mi++) {
        int row = m0 + wm + mi * 16 + r;
#pragma unroll
        for (int ni = 0; ni < 4; ni++) {
            int col = wn + ni * 8 + 2 * j;
            int gcol = n0 + col;
            if (gcol < Nout) {
                float bx = sbias[col], by = sbias[col + 1];
                *(float2*)(C + (size_t)row * ldc + gcol) =
                    make_float2(d[mi][ni][0] + bx, d[mi][ni][1] + by);
                *(float2*)(C + (size_t)(row + 8) * ldc + gcol) =
                    make_float2(d[mi][ni][2] + bx, d[mi][ni][3] + by);
            }
        }
    }

#undef LOAD_GLOBAL
#undef STORE_SMEM
#undef COMPUTE
}

// ---------------- zero ----------------
__global__ void zero_kernel(float* p, int n) {
    int i = blockIdx.x * blockDim.x + threadIdx.x;
    int stride = gridDim.x * blockDim.x;
    for (; i < n; i += stride) p[i] = 0.0f;
}

// ---------------- attention filters ----------------
__global__ void attn_kernel(const float* __restrict__ hdec,
                            const float* __restrict__ w_attn,
                            const float* __restrict__ b_attn,
                            float* __restrict__ Fx, float* __restrict__ Fy,
                            float* __restrict__ gma,
                            const float* __restrict__ henc,
                            float* __restrict__ encin, int copy_states)
{
    int b = blockIdx.x;
    int tid = threadIdx.x;
    __shared__ float red[5][129];
    __shared__ float p[5];
    __shared__ float Fbuf[NN * 64];
    __shared__ float rsum[NN];

    const float* h = hdec + (size_t)b * DEC;
    float acc[5] = {0.f, 0.f, 0.f, 0.f, 0.f};
    for (int k = tid; k < DEC; k += 128) {
        float hv = h[k];
#pragma unroll
        for (int jj = 0; jj < 5; jj++) acc[jj] += hv * w_attn[jj * DEC + k];
    }
#pragma unroll
    for (int jj = 0; jj < 5; jj++) red[jj][tid] = acc[jj];
    __syncthreads();
    if (tid < 5) {
        float s = 0.f;
        for (int i = 0; i < 128; i++) s += red[tid][i];
        p[tid] = s + b_attn[tid];
    }
    __syncthreads();

    float gx     = 32.5f * (p[0] + 1.0f);
    float gy     = 32.5f * (p[1] + 1.0f);
    float sigma2 = expf(p[2]);
    float delta  = (63.0f / 11.0f) * expf(p[3]);
    float gamma  = expf(p[4]);
    float inv2s2 = 1.0f / (2.0f * sigma2);

    for (int e = tid; e < NN * 64; e += 128) {
        int n = e >> 6, a = e & 63;
        float mu = ((float)n - 6.5f) * delta + gx;
        float t = ((float)a - mu) * inv2s2;
        Fbuf[e] = expf(-t * t);
    }
    __syncthreads();
    if (tid < NN) {
        float s = 0.f;
        for (int a = 0; a < 64; a++) s += Fbuf[tid * 64 + a];
        rsum[tid] = 1.0f / (s + 1e-9f);
    }
    __syncthreads();
    for (int e = tid; e < NN * 64; e += 128)
        Fx[(size_t)b * (NN * 64) + e] = Fbuf[e] * rsum[e >> 6];
    __syncthreads();

    for (int e = tid; e < NN * 64; e += 128) {
        int n = e >> 6, a = e & 63;
        float mu = ((float)n - 6.5f) * delta + gy;
        float t = ((float)a - mu) * inv2s2;
        Fbuf[e] = expf(-t * t);
    }
    __syncthreads();
    if (tid < NN) {
        float s = 0.f;
        for (int a = 0; a < 64; a++) s += Fbuf[tid * 64 + a];
        rsum[tid] = 1.0f / (s + 1e-9f);
    }
    __syncthreads();
    for (int e = tid; e < NN * 64; e += 128)
        Fy[(size_t)b * (NN * 64) + e] = Fbuf[e] * rsum[e >> 6];

    if (tid == 0) gma[b] = gamma;

    if (copy_states) {
        float* ei = encin + (size_t)b * 1088;
        const float* he = henc + (size_t)b * ENC;
        for (int k = tid; k < 400; k += 128) {
            ei[288 + k] = h[k];
            ei[688 + k] = he[k];
        }
    }
}

// ---------------- glimpse (read) ----------------
__global__ void glimpse_kernel(const float* __restrict__ x,
                               const float* __restrict__ c,
                               const float* __restrict__ Fxg,
                               const float* __restrict__ Fyg,
                               const float* __restrict__ gma,
                               float* __restrict__ encin)
{
    int b = blockIdx.x;
    int tid = threadIdx.x;
    __shared__ float xs[4096];
    __shared__ float xh[4096];
    __shared__ float sFy[NN * 64];
    __shared__ float sFx[NN * 65];
    __shared__ float tmp[2][NN * 64];

    const float* xb = x + (size_t)b * 4096;
    const float* cb = c + (size_t)b * 4096;
    for (int i = tid; i < 4096; i += 256) {
        float xv = xb[i];
        float cv = cb[i];
        xs[i] = xv;
        xh[i] = xv - sigm(cv);
    }
    for (int i = tid; i < NN * 64; i += 256) {
        sFy[i] = Fyg[(size_t)b * (NN * 64) + i];
        int n = i >> 6, a = i & 63;
        sFx[n * 65 + a] = Fxg[(size_t)b * (NN * 64) + i];
    }
    __syncthreads();

    for (int e = tid; e < 2 * NN * 64; e += 256) {
        int img = (e >= NN * 64) ? 1 : 0;
        int rem = e - img * NN * 64;
        int n = rem >> 6, a = rem & 63;
        const float* src = img ? xh : xs;
        const float* fyr = &sFy[n * 64];
        float acc = 0.f;
#pragma unroll 8
        for (int bi = 0; bi < 64; bi++) acc += fyr[bi] * src[bi * 64 + a];
        tmp[img][rem] = acc;
    }
    __syncthreads();

    float gamma = gma[b];
    for (int o = tid; o < 2 * NN * NN; o += 256) {
        int img = (o >= NN * NN) ? 1 : 0;
        int rem = o - img * NN * NN;
        int n = rem / NN, m = rem % NN;
        const float* tr = &tmp[img][n * 64];
        const float* fxr = &sFx[m * 65];
        float acc = 0.f;
#pragma unroll 8
        for (int a = 0; a < 64; a++) acc += tr[a] * fxr[a];
        encin[(size_t)b * 1088 + o] = acc * gamma;
    }
}

// ---------------- canvas write ----------------
__global__ void write_kernel(const float* __restrict__ wrg,
                             const float* __restrict__ Fxg,
                             const float* __restrict__ Fyg,
                             const float* __restrict__ gma,
                             float* __restrict__ c)
{
    int b = blockIdx.x;
    int tid = threadIdx.x;
    __shared__ float sFy[NN * 64];
    __shared__ float sFx[NN * 64];
    __shared__ float sw[NN * NN];
    __shared__ float tmp[NN * 64];

    for (int i = tid; i < NN * 64; i += 256) {
        sFy[i] = Fyg[(size_t)b * (NN * 64) + i];
        sFx[i] = Fxg[(size_t)b * (NN * 64) + i];
    }
    if (tid < NN * NN) sw[tid] = wrg[(size_t)b * (NN * NN) + tid];
    __syncthreads();

    for (int e = tid; e < NN * 64; e += 256) {
        int m = e >> 6, Bi = e & 63;
        float acc = 0.f;
#pragma unroll
        for (int n = 0; n < NN; n++) acc += sFy[n * 64 + Bi] * sw[n * NN + m];
        tmp[e] = acc;
    }
    __syncthreads();

    float invg = 1.0f / gma[b];
    float* cb = c + (size_t)b * 4096;
    for (int p = tid; p < 4096; p += 256) {
        int Bi = p >> 6, Ai = p & 63;
        float acc = 0.f;
#pragma unroll
        for (int m = 0; m < NN; m++) acc += tmp[m * 64 + Bi] * sFx[m * 64 + Ai];
        cb[p] += acc * invg;
    }
}

// ---------------- LSTM pointwise ----------------
__global__ void lstm_pw(const float* __restrict__ gates,
                        float* __restrict__ h, float* __restrict__ s)
{
    int idx = blockIdx.x * blockDim.x + threadIdx.x;
    int total = BATCH * 400;
    if (idx >= total) return;
    int b = idx / 400, u = idx - b * 400;
    const float* g = gates + (size_t)b * 1600;
    float gi = g[u], gf = g[400 + u], gg = g[800 + u], go = g[1200 + u];
    float sv = s[idx];
    float c2 = sigm(gf) * sv + sigm(gi) * tanhf(gg);
    float h2 = sigm(go) * tanhf(c2);
    s[idx] = c2;
    h[idx] = h2;
}

// ---------------- z + decoder input assembly (padded to 512) ----------------
__global__ void z_kernel(const float* __restrict__ musig,
                         const float* __restrict__ eps_t,
                         const float* __restrict__ hdec,
                         float* __restrict__ decin)
{
    int idx = blockIdx.x * blockDim.x + threadIdx.x;
    int total = BATCH * 512;
    if (idx >= total) return;
    int b = idx >> 9, j = idx & 511;
    float v;
    if (j < 100) {
        float mu = musig[(size_t)b * 200 + j];
        float ls = musig[(size_t)b * 200 + 100 + j];
        v = mu + expf(ls) * eps_t[(size_t)b * 100 + j];
    } else if (j < 500) {
        v = hdec[(size_t)b * 400 + (j - 100)];
    } else {
        v = 0.f;
    }
    decin[idx] = v;
}

// ---------------- host launcher ----------------
extern "C" void kernel_launch(void* const* d_in, const int* in_sizes, int n_in,
                              void* d_out, int out_size)
{
    const float* x        = (const float*)d_in[0];
    const float* eps      = (const float*)d_in[1];
    const float* w_enc_ih = (const float*)d_in[2];
    const float* w_enc_hh = (const float*)d_in[3];
    const float* b_enc_ih = (const float*)d_in[4];
    const float* b_enc_hh = (const float*)d_in[5];
    const float* w_dec_ih = (const float*)d_in[6];
    const float* w_dec_hh = (const float*)d_in[7];
    const float* b_dec_ih = (const float*)d_in[8];
    const float* b_dec_hh = (const float*)d_in[9];
    const float* w_mu     = (const float*)d_in[10];
    const float* b_mu     = (const float*)d_in[11];
    const float* w_sig    = (const float*)d_in[12];
    const float* b_sig    = (const float*)d_in[13];
    const float* w_attn   = (const float*)d_in[14];
    const float* b_attn   = (const float*)d_in[15];
    const float* w_write  = (const float*)d_in[16];
    const float* b_write  = (const float*)d_in[17];
    float* c = (float*)d_out;

    float *p_henc, *p_senc, *p_hdec, *p_sdec, *p_encin, *p_decin;
    float *p_gates, *p_musig, *p_Fx, *p_Fy, *p_gamma, *p_wr;
    cudaGetSymbolAddress((void**)&p_henc,  g_henc);
    cudaGetSymbolAddress((void**)&p_senc,  g_senc);
    cudaGetSymbolAddress((void**)&p_hdec,  g_hdec);
    cudaGetSymbolAddress((void**)&p_sdec,  g_sdec);
    cudaGetSymbolAddress((void**)&p_encin, g_encin);
    cudaGetSymbolAddress((void**)&p_decin, g_decin);
    cudaGetSymbolAddress((void**)&p_gates, g_gates);
    cudaGetSymbolAddress((void**)&p_musig, g_musig);
    cudaGetSymbolAddress((void**)&p_Fx,    g_Fx);
    cudaGetSymbolAddress((void**)&p_Fy,    g_Fy);
    cudaGetSymbolAddress((void**)&p_gamma, g_gamma);
    cudaGetSymbolAddress((void**)&p_wr,    g_wr);

    cudaFuncSetAttribute(gemm_mma, cudaFuncAttributeMaxDynamicSharedMemorySize,
                         GEMM_SMEM_BYTES);

    // init: zero canvas + states
    zero_kernel<<<4096, 256>>>(c, BATCH * AA * BB);
    zero_kernel<<<1024, 256>>>(p_henc, BATCH * ENC);
    zero_kernel<<<1024, 256>>>(p_senc, BATCH * ENC);
    zero_kernel<<<1024, 256>>>(p_hdec, BATCH * DEC);
    zero_kernel<<<1024, 256>>>(p_sdec, BATCH * DEC);

    dim3 grid_gate(25, 32);  // Nout=1600, M=4096
    dim3 grid_ms(2, 32);     // Nout=100
    dim3 grid_wr(3, 32);     // Nout=144

    for (int t = 0; t < T_STEPS; t++) {
        attn_kernel<<<BATCH, 128>>>(p_hdec, w_attn, b_attn, p_Fx, p_Fy, p_gamma,
                                    p_henc, p_encin, 1);
        glimpse_kernel<<<BATCH, 256>>>(x, c, p_Fx, p_Fy, p_gamma, p_encin);
        // encoder gates (3xTF32 mma.sync)
        gemm_mma<<<grid_gate, 256, GEMM_SMEM_BYTES>>>(
            p_encin, 1088, 1088, w_enc_ih, 688, w_enc_hh, 400,
            b_enc_ih, b_enc_hh, p_gates, 1600, 1600);
        lstm_pw<<<(BATCH * 400 + 255) / 256, 256>>>(p_gates, p_henc, p_senc);
        gemm_mma<<<grid_ms, 256, GEMM_SMEM_BYTES>>>(
            p_henc, 400, 400, w_mu, 400, (const float*)nullptr, 0,
            b_mu, (const float*)nullptr, p_musig, 200, 100);
        gemm_mma<<<grid_ms, 256, GEMM_SMEM_BYTES>>>(
            p_henc, 400, 400, w_sig, 400, (const float*)nullptr, 0,
            b_sig, (const float*)nullptr, p_musig + 100, 200, 100);
        z_kernel<<<(BATCH * 512 + 255) / 256, 256>>>(
            p_musig, eps + (size_t)t * BATCH * ZS, p_hdec, p_decin);
        // decoder gates (K padded 500->512 with zeros in decin)
        gemm_mma<<<grid_gate, 256, GEMM_SMEM_BYTES>>>(
            p_decin, 512, 512, w_dec_ih, 100, w_dec_hh, 400,
            b_dec_ih, b_dec_hh, p_gates, 1600, 1600);
        lstm_pw<<<(BATCH * 400 + 255) / 256, 256>>>(p_gates, p_hdec, p_sdec);
        attn_kernel<<<BATCH, 128>>>(p_hdec, w_attn, b_attn, p_Fx, p_Fy, p_gamma,
                                    p_henc, p_encin, 0);
        gemm_mma<<<grid_wr, 256, GEMM_SMEM_BYTES>>>(
            p_hdec, 400, 400, w_write, 400, (const float*)nullptr, 0,
            b_write, (const float*)nullptr, p_wr, 144, 144);
        write_kernel<<<BATCH, 256>>>(p_wr, p_Fx, p_Fy, p_gamma, c);
    }
}